// round 7
// baseline (speedup 1.0000x reference)
#include <cuda_runtime.h>
#include <cstdint>

// Problem constants
#define NFFT 8192
#define HALF 4096
#define GD   128
#define BC   16
#define KC   4
#define MC   4
#define PC   6
#define BKC  (BC*KC)   // 64
#define TFT  512       // threads per FFT block

// Smem swizzle for radix-8 strides: XOR (bits[3:6) ^ bits[6:9)) into bits[0:3).
// Injective (bits >=3 untouched); kills the 16-way conflict on stride-8 writes.
#define IX(i) ((i) ^ (((((i) >> 3) ^ ((i) >> 6))) & 7))

// Scratch (device globals — no allocation allowed)
__device__ float2   g_spec[BKC * 2 * NFFT];      // packed forward spectra, 8.4 MB
__device__ float    g_cc[BKC * PC * NFFT];       // per-pair fftshifted cc, 12.6 MB
__device__ unsigned g_maxenc[BKC];               // per-(b,k) max, ordered-uint encoded

__device__ __forceinline__ float2 cmulf(float2 a, float2 b) {
    return make_float2(a.x * b.x - a.y * b.y, a.x * b.y + a.y * b.x);
}
__device__ __forceinline__ float2 caddf(float2 a, float2 b) { return make_float2(a.x + b.x, a.y + b.y); }
__device__ __forceinline__ float2 csubf(float2 a, float2 b) { return make_float2(a.x - b.x, a.y - b.y); }

// ordered-uint encoding for float atomicMax (handles negatives)
__device__ __forceinline__ unsigned enc_f(float f) {
    unsigned u = __float_as_uint(f);
    return (u & 0x80000000u) ? ~u : (u | 0x80000000u);
}
__device__ __forceinline__ float dec_f(unsigned e) {
    unsigned u = (e & 0x80000000u) ? (e & 0x7fffffffu) : ~e;
    return __uint_as_float(u);
}
#define ENC_NEG_INF 0x007fffffu   // enc(-inf)

// Build accurate twiddle table: tw[k] = exp(-2*pi*i*k/NFFT), k in [0, NFFT/2)
__device__ __forceinline__ void build_twiddles(float2* tw) {
    for (int k = threadIdx.x; k < NFFT / 2; k += TFT) {
        float s, c;
        sincospif(-(float)k * (1.0f / (float)HALF), &s, &c);  // angle = -pi*k/4096
        tw[k] = make_float2(c, s);
    }
}

// ---------------------------------------------------------------------------
// Shared-memory Stockham FFT, 8192 points, 512 threads.
// 4 radix-8 stages (ls = 0,3,6,9) + 1 trivial radix-2. 5 smem round trips.
// w1 from table; w2..w7 by multiplication. INV toggles conjugation.
// ---------------------------------------------------------------------------
template <bool INV>
__device__ float2* block_fft(float2* b0, float2* b1, const float2* __restrict__ tw) {
    float2* src = b0;
    float2* dst = b1;
    const float RS2 = 0.70710678118654752f;

    #pragma unroll
    for (int ls = 0; ls <= 9; ls += 3) {       // s = 1, 8, 64, 512
        #pragma unroll
        for (int it = 0; it < (NFFT / 8) / TFT; it++) {
            int u = it * TFT + threadIdx.x;    // butterfly index in [0, 1024)
            int p = u >> ls;

            float2 x0 = src[IX(u)];
            float2 x1 = src[IX(u + 1024)];
            float2 x2 = src[IX(u + 2048)];
            float2 x3 = src[IX(u + 3072)];
            float2 x4 = src[IX(u + 4096)];
            float2 x5 = src[IX(u + 5120)];
            float2 x6 = src[IX(u + 6144)];
            float2 x7 = src[IX(u + 7168)];

            // 8-point DFT (DIT split even/odd into two 4-pt DFTs)
            float2 t0 = caddf(x0, x4), t1 = csubf(x0, x4);
            float2 t2 = caddf(x2, x6), t3 = csubf(x2, x6);
            float2 t4 = caddf(x1, x5), t5 = csubf(x1, x5);
            float2 t6 = caddf(x3, x7), t7 = csubf(x3, x7);
            // rotate by -i (fwd) / +i (inv)
            float2 r3 = INV ? make_float2(-t3.y, t3.x) : make_float2(t3.y, -t3.x);
            float2 r7 = INV ? make_float2(-t7.y, t7.x) : make_float2(t7.y, -t7.x);
            float2 E0 = caddf(t0, t2), E2 = csubf(t0, t2);
            float2 E1 = caddf(t1, r3), E3 = csubf(t1, r3);
            float2 O0 = caddf(t4, t6), O2 = csubf(t4, t6);
            float2 O1 = caddf(t5, r7), O3 = csubf(t5, r7);
            // omega8^r on O1, O2, O3
            float2 o1 = INV ? make_float2(RS2 * (O1.x - O1.y), RS2 * (O1.x + O1.y))
                            : make_float2(RS2 * (O1.x + O1.y), RS2 * (O1.y - O1.x));
            float2 o2 = INV ? make_float2(-O2.y, O2.x) : make_float2(O2.y, -O2.x);
            float2 o3 = INV ? make_float2(-RS2 * (O3.x + O3.y), RS2 * (O3.x - O3.y))
                            : make_float2(RS2 * (O3.y - O3.x), -RS2 * (O3.x + O3.y));

            int s = 1 << ls;
            int j = u + 7 * (p << ls);         // q + 8*s*p

            float2 w1 = tw[p << ls];
            if (INV) w1.y = -w1.y;
            float2 w2 = cmulf(w1, w1);
            float2 w3 = cmulf(w2, w1);
            float2 w4 = cmulf(w2, w2);

            dst[IX(j)]         = caddf(E0, O0);
            dst[IX(j + s)]     = cmulf(caddf(E1, o1), w1);
            dst[IX(j + 2 * s)] = cmulf(caddf(E2, o2), w2);
            dst[IX(j + 3 * s)] = cmulf(caddf(E3, o3), w3);
            dst[IX(j + 4 * s)] = cmulf(csubf(E0, O0), w4);
            dst[IX(j + 5 * s)] = cmulf(csubf(E1, o1), cmulf(w4, w1));
            dst[IX(j + 6 * s)] = cmulf(csubf(E2, o2), cmulf(w4, w2));
            dst[IX(j + 7 * s)] = cmulf(csubf(E3, o3), cmulf(w4, w3));
        }
        __syncthreads();
        float2* tmp = src; src = dst; dst = tmp;
    }

    // final radix-2 stage, s = 4096: p = 0 -> twiddle = 1
    #pragma unroll
    for (int it = 0; it < (NFFT / 2) / TFT; it++) {
        int t = it * TFT + threadIdx.x;
        float2 a = src[IX(t)];
        float2 b = src[IX(t + NFFT / 2)];
        dst[IX(t)]            = caddf(a, b);
        dst[IX(t + NFFT / 2)] = csubf(a, b);
    }
    __syncthreads();
    return dst;
}

// ---------------------------------------------------------------------------
// Kernel 1: forward FFT of packed mic pairs.
// Block g in [0,128): bk = g>>1, h = g&1 -> FFT(mic[2h] + i*mic[2h+1])
// Block 0 also resets the per-(b,k) max accumulators.
// ---------------------------------------------------------------------------
__global__ __launch_bounds__(TFT, 1)
void fwd_fft_kernel(const float* __restrict__ signal) {
    extern __shared__ float2 sm[];
    float2* b0 = sm;
    float2* b1 = sm + NFFT;
    float2* tw = sm + 2 * NFFT;

    if (blockIdx.x == 0 && threadIdx.x < BKC)
        g_maxenc[threadIdx.x] = ENC_NEG_INF;

    build_twiddles(tw);

    int g  = blockIdx.x;
    int bk = g >> 1;
    int h  = g & 1;
    const float* s0 = signal + ((size_t)bk * MC + 2 * h) * NFFT;
    const float* s1 = s0 + NFFT;

    for (int i = threadIdx.x; i < NFFT; i += TFT)
        b0[IX(i)] = make_float2(s0[i], s1[i]);
    __syncthreads();

    float2* res = block_fft<false>(b0, b1, tw);

    float2* out = &g_spec[(size_t)g * NFFT];
    for (int i = threadIdx.x; i < NFFT; i += TFT)
        out[i] = res[IX(i)];
}

// ---------------------------------------------------------------------------
// Kernel 2: cross-spectra + PHAT for two pairs, packed inverse FFT,
// fftshift + scale, write cc.
// Block g in [0,192): bk = g/3, pp = g%3; pairs 2pp and 2pp+1.
// ---------------------------------------------------------------------------
template <int IA, int JA, int IB, int JB>
__device__ void build_phat_packed(const float2* __restrict__ Za,
                                  const float2* __restrict__ Zb,
                                  float2* __restrict__ w) {
    for (int f = threadIdx.x; f < NFFT; f += TFT) {
        int fr = (NFFT - f) & (NFFT - 1);
        float2 za  = Za[f],  zar = Za[fr];
        float2 zb  = Zb[f],  zbr = Zb[fr];
        // X0 = (Za + conj(ZaR))/2 ; X1 = (Za - conj(ZaR))/(2i)
        float2 X[4];
        X[0] = make_float2(0.5f * (za.x + zar.x),  0.5f * (za.y - zar.y));
        X[1] = make_float2(0.5f * (za.y + zar.y), -0.5f * (za.x - zar.x));
        X[2] = make_float2(0.5f * (zb.x + zbr.x),  0.5f * (zb.y - zbr.y));
        X[3] = make_float2(0.5f * (zb.y + zbr.y), -0.5f * (zb.x - zbr.x));

        float2 pa, pb;
        {
            float2 xi = X[IA], xj = X[JA];
            float2 c = make_float2(xi.x * xj.x + xi.y * xj.y,
                                   xi.y * xj.x - xi.x * xj.y);   // Xi * conj(Xj)
            float mag = sqrtf(c.x * c.x + c.y * c.y);
            float inv = 1.0f / fmaxf(mag, 1e-9f);
            pa = make_float2(c.x * inv, c.y * inv);
        }
        {
            float2 xi = X[IB], xj = X[JB];
            float2 c = make_float2(xi.x * xj.x + xi.y * xj.y,
                                   xi.y * xj.x - xi.x * xj.y);
            float mag = sqrtf(c.x * c.x + c.y * c.y);
            float inv = 1.0f / fmaxf(mag, 1e-9f);
            pb = make_float2(c.x * inv, c.y * inv);
        }
        // w = P_A + i * P_B  (both Hermitian -> one complex ifft gives both cc's)
        w[IX(f)] = make_float2(pa.x - pb.y, pa.y + pb.x);
    }
}

__global__ __launch_bounds__(TFT, 1)
void cross_ifft_kernel() {
    extern __shared__ float2 sm[];
    float2* b0 = sm;
    float2* b1 = sm + NFFT;
    float2* tw = sm + 2 * NFFT;

    build_twiddles(tw);

    int g  = blockIdx.x;
    int bk = g / 3;
    int pp = g - 3 * bk;

    const float2* Za = &g_spec[(size_t)(bk * 2 + 0) * NFFT];
    const float2* Zb = &g_spec[(size_t)(bk * 2 + 1) * NFFT];

    // pp=0 -> pairs (0,1),(0,2); pp=1 -> (0,3),(1,2); pp=2 -> (1,3),(2,3)
    if      (pp == 0) build_phat_packed<0, 1, 0, 2>(Za, Zb, b0);
    else if (pp == 1) build_phat_packed<0, 3, 1, 2>(Za, Zb, b0);
    else              build_phat_packed<1, 3, 2, 3>(Za, Zb, b0);
    __syncthreads();

    float2* res = block_fft<true>(b0, b1, tw);  // un-normalized ifft

    // fftshift (index ^ 4096) + 1/N scale, write both cc rows
    const float invN = 1.0f / (float)NFFT;
    int pA = 2 * pp, pB = pA + 1;
    float* CA = &g_cc[((size_t)bk * PC + pA) * NFFT];
    float* CB = &g_cc[((size_t)bk * PC + pB) * NFFT];
    for (int idx = threadIdx.x; idx < NFFT; idx += TFT) {
        float2 z = res[IX(idx ^ HALF)];
        CA[idx] = z.x * invN;
        CB[idx] = z.y * invN;
    }
}

// ---------------------------------------------------------------------------
// Kernel 3: SRP grid accumulation + per-(b,k) max via atomicMax.
// Block = (bk, gi); thread = gj.
// Delay path mimics XLA:CPU partial-fast-math codegen — DO NOT CHANGE:
//   dist = sqrt( fma(dx, dx, dy*dy) )
//   x    = (d_i - d_j) * fl(16000/343)
//   delay = roundeven(x) + N/2
// ---------------------------------------------------------------------------
__global__ __launch_bounds__(GD)
void grid_kernel(const float* __restrict__ mic,
                 const float* __restrict__ room,
                 float* __restrict__ out) {
    __shared__ float wred[4];
    int bid = blockIdx.x;
    int bk  = bid >> 7;          // /128
    int gi  = bid & 127;
    int b   = bk >> 2;           // /K
    int gj  = threadIdx.x;

    const float step = 1.0f / 127.0f;  // fl(1/127); matches jnp.linspace step
    float tx = __fmul_rn((float)gi, step);
    float ty = __fmul_rn((float)gj, step);
    float gx = __fmul_rn(__ldg(&room[b * 3 + 0]), tx);
    float gy = __fmul_rn(__ldg(&room[b * 3 + 1]), ty);

    float d[4];
    #pragma unroll
    for (int m = 0; m < 4; m++) {
        float mx = __ldg(&mic[((size_t)bk * MC + m) * 3 + 0]);
        float my = __ldg(&mic[((size_t)bk * MC + m) * 3 + 1]);
        float dx = __fsub_rn(gx, mx);
        float dy = __fsub_rn(gy, my);
        float dy2 = __fmul_rn(dy, dy);
        d[m] = sqrtf(__fmaf_rn(dx, dx, dy2));   // LLVM contraction order
    }

    const float SCALE = __fdiv_rn(16000.0f, 343.0f);  // fl(16000/343)

    const int ii[PC] = {0, 0, 0, 1, 1, 2};
    const int jj[PC] = {1, 2, 3, 2, 3, 3};
    float acc = 0.0f;
    #pragma unroll
    for (int p = 0; p < PC; p++) {
        float x     = __fmul_rn(__fsub_rn(d[ii[p]], d[jj[p]]), SCALE);
        int   delay = (int)rintf(x) + HALF;                   // half-even
        const float* C = &g_cc[((size_t)bk * PC + p) * NFFT];
        int base = delay - 5;                                 // offs = -5..+4
        float v = 0.0f;
        #pragma unroll
        for (int o = 0; o < 10; o++) {
            int id = min(max(base + o, 0), NFFT - 1);
            v += __ldg(&C[id]);
        }
        acc += v;
    }
    out[(size_t)bk * (GD * GD) + gi * GD + gj] = acc;

    // block max -> atomicMax (ordered-uint; max is order-independent -> deterministic)
    float mx = acc;
    #pragma unroll
    for (int o = 16; o; o >>= 1)
        mx = fmaxf(mx, __shfl_xor_sync(0xffffffffu, mx, o));
    if ((threadIdx.x & 31) == 0) wred[threadIdx.x >> 5] = mx;
    __syncthreads();
    if (threadIdx.x == 0) {
        mx = fmaxf(fmaxf(wred[0], wred[1]), fmaxf(wred[2], wred[3]));
        atomicMax(&g_maxenc[bk], enc_f(mx));
    }
}

// ---------------------------------------------------------------------------
// Kernel 4: wide vectorized divide by per-(b,k) max (R5 best-measured shape).
// 1024 blocks x 256 threads, one float4 per thread.
// ---------------------------------------------------------------------------
__global__ __launch_bounds__(256)
void divide_kernel(float* __restrict__ out) {
    int i  = blockIdx.x * 256 + threadIdx.x;   // float4 index, [0, 256K)
    int bk = i >> 12;                          // 4096 float4 per (b,k)
    float m = dec_f(g_maxenc[bk]);
    float4 v = reinterpret_cast<float4*>(out)[i];
    v.x = __fdiv_rn(v.x, m);
    v.y = __fdiv_rn(v.y, m);
    v.z = __fdiv_rn(v.z, m);
    v.w = __fdiv_rn(v.w, m);
    reinterpret_cast<float4*>(out)[i] = v;
}

// ---------------------------------------------------------------------------
extern "C" void kernel_launch(void* const* d_in, const int* in_sizes, int n_in,
                              void* d_out, int out_size) {
    const float* signal = (const float*)d_in[0];  // (B,K,M,N)
    const float* mic    = (const float*)d_in[1];  // (B,K,M,3)
    const float* room   = (const float*)d_in[2];  // (B,3)
    float* out = (float*)d_out;                   // (B,K,G*G)

    const int smem = (2 * NFFT + NFFT / 2) * (int)sizeof(float2);  // 160 KB
    cudaFuncSetAttribute(fwd_fft_kernel,    cudaFuncAttributeMaxDynamicSharedMemorySize, smem);
    cudaFuncSetAttribute(cross_ifft_kernel, cudaFuncAttributeMaxDynamicSharedMemorySize, smem);

    fwd_fft_kernel<<<BKC * 2, TFT, smem>>>(signal);
    cross_ifft_kernel<<<BKC * 3, TFT, smem>>>();
    grid_kernel<<<BKC * GD, GD>>>(mic, room, out);
    divide_kernel<<<(BKC * GD * GD / 4) / 256, 256>>>(out);
}

// round 8
// speedup vs baseline: 1.1147x; 1.1147x over previous
#include <cuda_runtime.h>
#include <cstdint>

// Problem constants
#define NFFT 8192
#define HALF 4096
#define GD   128
#define BC   16
#define KC   4
#define MC   4
#define PC   6
#define BKC  (BC*KC)   // 64
#define TFT  512       // threads per FFT block

// Smem swizzle for radix-8 strides: XOR (bits[3:6) ^ bits[6:9)) into bits[0:3).
#define IX(i) ((i) ^ (((((i) >> 3) ^ ((i) >> 6))) & 7))

// Scratch (device globals — no allocation allowed)
__device__ float2   g_spec[BKC * 2 * NFFT];      // packed forward spectra, 8.4 MB
__device__ float    g_cc[BKC * PC * NFFT];       // per-pair fftshifted cc, 12.6 MB
__device__ unsigned g_maxenc[BKC];               // per-(b,k) max, ordered-uint encoded

__device__ __forceinline__ float2 cmulf(float2 a, float2 b) {
    return make_float2(a.x * b.x - a.y * b.y, a.x * b.y + a.y * b.x);
}
__device__ __forceinline__ float2 caddf(float2 a, float2 b) { return make_float2(a.x + b.x, a.y + b.y); }
__device__ __forceinline__ float2 csubf(float2 a, float2 b) { return make_float2(a.x - b.x, a.y - b.y); }

// ordered-uint encoding for float atomicMax (handles negatives)
__device__ __forceinline__ unsigned enc_f(float f) {
    unsigned u = __float_as_uint(f);
    return (u & 0x80000000u) ? ~u : (u | 0x80000000u);
}
__device__ __forceinline__ float dec_f(unsigned e) {
    unsigned u = (e & 0x80000000u) ? (e & 0x7fffffffu) : ~e;
    return __uint_as_float(u);
}
#define ENC_NEG_INF 0x007fffffu   // enc(-inf)

// Twiddle table: tw[k] = exp(-2*pi*i*k/NFFT), k in [0, 1024).
// Radix-8 stages only index tw[p<<ls] with p<<ls < 1024.
#define TWN 1024
__device__ __forceinline__ void build_twiddles(float2* tw) {
    for (int k = threadIdx.x; k < TWN; k += TFT) {
        float s, c;
        sincospif(-(float)k * (1.0f / (float)HALF), &s, &c);  // angle = -pi*k/4096
        tw[k] = make_float2(c, s);
    }
}

// ---------------------------------------------------------------------------
// In-place shared-memory Stockham FFT, 8192 points, 512 threads.
// 4 radix-8 stages + 1 trivial radix-2. Single 64KB buffer:
// each stage reads all its inputs to registers, barriers, then writes.
// (Stockham stages are bijective read/write over all N -> safe in place.)
// ---------------------------------------------------------------------------
template <bool INV>
__device__ void block_fft(float2* buf, const float2* __restrict__ tw) {
    const float RS2 = 0.70710678118654752f;

    #pragma unroll
    for (int ls = 0; ls <= 9; ls += 3) {       // s = 1, 8, 64, 512
        float2 X[2][8];
        // phase 1: read both butterflies into registers
        #pragma unroll
        for (int h = 0; h < 2; h++) {
            int u = threadIdx.x + h * TFT;
            #pragma unroll
            for (int k = 0; k < 8; k++)
                X[h][k] = buf[IX(u + k * 1024)];
        }
        __syncthreads();
        // phase 2: butterfly + twiddle + write back (in place)
        #pragma unroll
        for (int h = 0; h < 2; h++) {
            int u = threadIdx.x + h * TFT;
            int p = u >> ls;

            float2 x0 = X[h][0], x1 = X[h][1], x2 = X[h][2], x3 = X[h][3];
            float2 x4 = X[h][4], x5 = X[h][5], x6 = X[h][6], x7 = X[h][7];

            float2 t0 = caddf(x0, x4), t1 = csubf(x0, x4);
            float2 t2 = caddf(x2, x6), t3 = csubf(x2, x6);
            float2 t4 = caddf(x1, x5), t5 = csubf(x1, x5);
            float2 t6 = caddf(x3, x7), t7 = csubf(x3, x7);
            float2 r3 = INV ? make_float2(-t3.y, t3.x) : make_float2(t3.y, -t3.x);
            float2 r7 = INV ? make_float2(-t7.y, t7.x) : make_float2(t7.y, -t7.x);
            float2 E0 = caddf(t0, t2), E2 = csubf(t0, t2);
            float2 E1 = caddf(t1, r3), E3 = csubf(t1, r3);
            float2 O0 = caddf(t4, t6), O2 = csubf(t4, t6);
            float2 O1 = caddf(t5, r7), O3 = csubf(t5, r7);
            float2 o1 = INV ? make_float2(RS2 * (O1.x - O1.y), RS2 * (O1.x + O1.y))
                            : make_float2(RS2 * (O1.x + O1.y), RS2 * (O1.y - O1.x));
            float2 o2 = INV ? make_float2(-O2.y, O2.x) : make_float2(O2.y, -O2.x);
            float2 o3 = INV ? make_float2(-RS2 * (O3.x + O3.y), RS2 * (O3.x - O3.y))
                            : make_float2(RS2 * (O3.y - O3.x), -RS2 * (O3.x + O3.y));

            int s = 1 << ls;
            int j = u + 7 * (p << ls);         // q + 8*s*p

            float2 w1 = tw[p << ls];
            if (INV) w1.y = -w1.y;
            float2 w2 = cmulf(w1, w1);
            float2 w3 = cmulf(w2, w1);
            float2 w4 = cmulf(w2, w2);

            buf[IX(j)]         = caddf(E0, O0);
            buf[IX(j + s)]     = cmulf(caddf(E1, o1), w1);
            buf[IX(j + 2 * s)] = cmulf(caddf(E2, o2), w2);
            buf[IX(j + 3 * s)] = cmulf(caddf(E3, o3), w3);
            buf[IX(j + 4 * s)] = cmulf(csubf(E0, O0), w4);
            buf[IX(j + 5 * s)] = cmulf(csubf(E1, o1), cmulf(w4, w1));
            buf[IX(j + 6 * s)] = cmulf(csubf(E2, o2), cmulf(w4, w2));
            buf[IX(j + 7 * s)] = cmulf(csubf(E3, o3), cmulf(w4, w3));
        }
        __syncthreads();
    }

    // final radix-2 stage, s = 4096, twiddle = 1.
    // Pairs (t, t+4096) are read AND written by the same thread -> in-place safe.
    #pragma unroll
    for (int it = 0; it < (NFFT / 2) / TFT; it++) {
        int t = it * TFT + threadIdx.x;
        float2 a = buf[IX(t)];
        float2 b = buf[IX(t + NFFT / 2)];
        buf[IX(t)]            = caddf(a, b);
        buf[IX(t + NFFT / 2)] = csubf(a, b);
    }
    __syncthreads();
}

// ---------------------------------------------------------------------------
// Kernel 1: forward FFT of packed mic pairs.
// Block g in [0,128): bk = g>>1, h = g&1 -> FFT(mic[2h] + i*mic[2h+1])
// Block 0 also resets the per-(b,k) max accumulators.
// ---------------------------------------------------------------------------
__global__ __launch_bounds__(TFT, 2)
void fwd_fft_kernel(const float* __restrict__ signal) {
    extern __shared__ float2 sm[];
    float2* buf = sm;
    float2* tw  = sm + NFFT;

    if (blockIdx.x == 0 && threadIdx.x < BKC)
        g_maxenc[threadIdx.x] = ENC_NEG_INF;

    build_twiddles(tw);

    int g  = blockIdx.x;
    int bk = g >> 1;
    int h  = g & 1;
    const float* s0 = signal + ((size_t)bk * MC + 2 * h) * NFFT;
    const float* s1 = s0 + NFFT;

    for (int i = threadIdx.x; i < NFFT; i += TFT)
        buf[IX(i)] = make_float2(s0[i], s1[i]);
    __syncthreads();

    block_fft<false>(buf, tw);

    float2* out = &g_spec[(size_t)g * NFFT];
    for (int i = threadIdx.x; i < NFFT; i += TFT)
        out[i] = buf[IX(i)];
}

// ---------------------------------------------------------------------------
// Kernel 2: cross-spectra + PHAT for two pairs, packed inverse FFT,
// fftshift + scale, write cc.
// Block g in [0,192): bk = g/3, pp = g%3; pairs 2pp and 2pp+1.
// ---------------------------------------------------------------------------
template <int IA, int JA, int IB, int JB>
__device__ void build_phat_packed(const float2* __restrict__ Za,
                                  const float2* __restrict__ Zb,
                                  float2* __restrict__ w) {
    for (int f = threadIdx.x; f < NFFT; f += TFT) {
        int fr = (NFFT - f) & (NFFT - 1);
        float2 za  = Za[f],  zar = Za[fr];
        float2 zb  = Zb[f],  zbr = Zb[fr];
        // X0 = (Za + conj(ZaR))/2 ; X1 = (Za - conj(ZaR))/(2i)
        float2 X[4];
        X[0] = make_float2(0.5f * (za.x + zar.x),  0.5f * (za.y - zar.y));
        X[1] = make_float2(0.5f * (za.y + zar.y), -0.5f * (za.x - zar.x));
        X[2] = make_float2(0.5f * (zb.x + zbr.x),  0.5f * (zb.y - zbr.y));
        X[3] = make_float2(0.5f * (zb.y + zbr.y), -0.5f * (zb.x - zbr.x));

        float2 pa, pb;
        {
            float2 xi = X[IA], xj = X[JA];
            float2 c = make_float2(xi.x * xj.x + xi.y * xj.y,
                                   xi.y * xj.x - xi.x * xj.y);   // Xi * conj(Xj)
            float mag = sqrtf(c.x * c.x + c.y * c.y);
            float inv = 1.0f / fmaxf(mag, 1e-9f);
            pa = make_float2(c.x * inv, c.y * inv);
        }
        {
            float2 xi = X[IB], xj = X[JB];
            float2 c = make_float2(xi.x * xj.x + xi.y * xj.y,
                                   xi.y * xj.x - xi.x * xj.y);
            float mag = sqrtf(c.x * c.x + c.y * c.y);
            float inv = 1.0f / fmaxf(mag, 1e-9f);
            pb = make_float2(c.x * inv, c.y * inv);
        }
        // w = P_A + i * P_B  (both Hermitian -> one complex ifft gives both cc's)
        w[IX(f)] = make_float2(pa.x - pb.y, pa.y + pb.x);
    }
}

__global__ __launch_bounds__(TFT, 2)
void cross_ifft_kernel() {
    extern __shared__ float2 sm[];
    float2* buf = sm;
    float2* tw  = sm + NFFT;

    build_twiddles(tw);

    int g  = blockIdx.x;
    int bk = g / 3;
    int pp = g - 3 * bk;

    const float2* Za = &g_spec[(size_t)(bk * 2 + 0) * NFFT];
    const float2* Zb = &g_spec[(size_t)(bk * 2 + 1) * NFFT];

    // pp=0 -> pairs (0,1),(0,2); pp=1 -> (0,3),(1,2); pp=2 -> (1,3),(2,3)
    if      (pp == 0) build_phat_packed<0, 1, 0, 2>(Za, Zb, buf);
    else if (pp == 1) build_phat_packed<0, 3, 1, 2>(Za, Zb, buf);
    else              build_phat_packed<1, 3, 2, 3>(Za, Zb, buf);
    __syncthreads();

    block_fft<true>(buf, tw);  // un-normalized ifft, in place

    // fftshift (index ^ 4096) + 1/N scale, write both cc rows
    const float invN = 1.0f / (float)NFFT;
    int pA = 2 * pp, pB = pA + 1;
    float* CA = &g_cc[((size_t)bk * PC + pA) * NFFT];
    float* CB = &g_cc[((size_t)bk * PC + pB) * NFFT];
    for (int idx = threadIdx.x; idx < NFFT; idx += TFT) {
        float2 z = buf[IX(idx ^ HALF)];
        CA[idx] = z.x * invN;
        CB[idx] = z.y * invN;
    }
}

// ---------------------------------------------------------------------------
// Kernel 3: SRP grid accumulation + per-(b,k) max via atomicMax.
// Block = (bk, gi); thread = gj.
// Delay path mimics XLA:CPU partial-fast-math codegen — DO NOT CHANGE:
//   dist = sqrt( fma(dx, dx, dy*dy) )
//   x    = (d_i - d_j) * fl(16000/343)
//   delay = roundeven(x) + N/2
// ---------------------------------------------------------------------------
__global__ __launch_bounds__(GD)
void grid_kernel(const float* __restrict__ mic,
                 const float* __restrict__ room,
                 float* __restrict__ out) {
    __shared__ float wred[4];
    int bid = blockIdx.x;
    int bk  = bid >> 7;          // /128
    int gi  = bid & 127;
    int b   = bk >> 2;           // /K
    int gj  = threadIdx.x;

    const float step = 1.0f / 127.0f;  // fl(1/127); matches jnp.linspace step
    float tx = __fmul_rn((float)gi, step);
    float ty = __fmul_rn((float)gj, step);
    float gx = __fmul_rn(__ldg(&room[b * 3 + 0]), tx);
    float gy = __fmul_rn(__ldg(&room[b * 3 + 1]), ty);

    float d[4];
    #pragma unroll
    for (int m = 0; m < 4; m++) {
        float mx = __ldg(&mic[((size_t)bk * MC + m) * 3 + 0]);
        float my = __ldg(&mic[((size_t)bk * MC + m) * 3 + 1]);
        float dx = __fsub_rn(gx, mx);
        float dy = __fsub_rn(gy, my);
        float dy2 = __fmul_rn(dy, dy);
        d[m] = sqrtf(__fmaf_rn(dx, dx, dy2));   // LLVM contraction order
    }

    const float SCALE = __fdiv_rn(16000.0f, 343.0f);  // fl(16000/343)

    const int ii[PC] = {0, 0, 0, 1, 1, 2};
    const int jj[PC] = {1, 2, 3, 2, 3, 3};
    float acc = 0.0f;
    #pragma unroll
    for (int p = 0; p < PC; p++) {
        float x     = __fmul_rn(__fsub_rn(d[ii[p]], d[jj[p]]), SCALE);
        int   delay = (int)rintf(x) + HALF;                   // half-even
        const float* C = &g_cc[((size_t)bk * PC + p) * NFFT];
        int base = delay - 5;                                 // offs = -5..+4
        float v = 0.0f;
        #pragma unroll
        for (int o = 0; o < 10; o++) {
            int id = min(max(base + o, 0), NFFT - 1);
            v += __ldg(&C[id]);
        }
        acc += v;
    }
    out[(size_t)bk * (GD * GD) + gi * GD + gj] = acc;

    // block max -> atomicMax (ordered-uint; max is order-independent -> deterministic)
    float mx = acc;
    #pragma unroll
    for (int o = 16; o; o >>= 1)
        mx = fmaxf(mx, __shfl_xor_sync(0xffffffffu, mx, o));
    if ((threadIdx.x & 31) == 0) wred[threadIdx.x >> 5] = mx;
    __syncthreads();
    if (threadIdx.x == 0) {
        mx = fmaxf(fmaxf(wred[0], wred[1]), fmaxf(wred[2], wred[3]));
        atomicMax(&g_maxenc[bk], enc_f(mx));
    }
}

// ---------------------------------------------------------------------------
// Kernel 4: wide vectorized divide by per-(b,k) max (R5 best-measured shape).
// 1024 blocks x 256 threads, one float4 per thread.
// ---------------------------------------------------------------------------
__global__ __launch_bounds__(256)
void divide_kernel(float* __restrict__ out) {
    int i  = blockIdx.x * 256 + threadIdx.x;   // float4 index, [0, 256K)
    int bk = i >> 12;                          // 4096 float4 per (b,k)
    float m = dec_f(g_maxenc[bk]);
    float4 v = reinterpret_cast<float4*>(out)[i];
    v.x = __fdiv_rn(v.x, m);
    v.y = __fdiv_rn(v.y, m);
    v.z = __fdiv_rn(v.z, m);
    v.w = __fdiv_rn(v.w, m);
    reinterpret_cast<float4*>(out)[i] = v;
}

// ---------------------------------------------------------------------------
extern "C" void kernel_launch(void* const* d_in, const int* in_sizes, int n_in,
                              void* d_out, int out_size) {
    const float* signal = (const float*)d_in[0];  // (B,K,M,N)
    const float* mic    = (const float*)d_in[1];  // (B,K,M,3)
    const float* room   = (const float*)d_in[2];  // (B,3)
    float* out = (float*)d_out;                   // (B,K,G*G)

    const int smem = (NFFT + TWN) * (int)sizeof(float2);  // 72 KB
    cudaFuncSetAttribute(fwd_fft_kernel,    cudaFuncAttributeMaxDynamicSharedMemorySize, smem);
    cudaFuncSetAttribute(cross_ifft_kernel, cudaFuncAttributeMaxDynamicSharedMemorySize, smem);

    fwd_fft_kernel<<<BKC * 2, TFT, smem>>>(signal);
    cross_ifft_kernel<<<BKC * 3, TFT, smem>>>();
    grid_kernel<<<BKC * GD, GD>>>(mic, room, out);
    divide_kernel<<<(BKC * GD * GD / 4) / 256, 256>>>(out);
}

// round 9
// speedup vs baseline: 1.1383x; 1.0211x over previous
#include <cuda_runtime.h>
#include <cstdint>

// Problem constants
#define NFFT 8192
#define HALF 4096
#define GD   128
#define BC   16
#define KC   4
#define MC   4
#define PC   6
#define BKC  (BC*KC)   // 64
#define TFT  512       // threads per FFT block

// Compact cc window: delays live in 4096 +/- 396, band +/-5 -> [3695, 4497).
// Store [3648, 4544) = 896 lags (margin 48 each side).
#define CCLO 3648
#define CCN  896

// Smem swizzle: XOR (bits[3:6) ^ bits[6:9)) into bits[0:3).
// Base-preserving for any base that is a multiple of 1024.
#define IX(i) ((i) ^ (((((i) >> 3) ^ ((i) >> 6))) & 7))

// Scratch (device globals — no allocation allowed)
__device__ float2   g_spec[BKC * 2 * NFFT];      // packed forward spectra, 8.4 MB
__device__ float    g_cc[BKC * PC * CCN];        // per-pair compact cc, 1.4 MB
__device__ unsigned g_maxenc[BKC];               // per-(b,k) max, ordered-uint encoded

__device__ __forceinline__ float2 cmulf(float2 a, float2 b) {
    return make_float2(a.x * b.x - a.y * b.y, a.x * b.y + a.y * b.x);
}
__device__ __forceinline__ float2 caddf(float2 a, float2 b) { return make_float2(a.x + b.x, a.y + b.y); }
__device__ __forceinline__ float2 csubf(float2 a, float2 b) { return make_float2(a.x - b.x, a.y - b.y); }

// ordered-uint encoding for float atomicMax (handles negatives)
__device__ __forceinline__ unsigned enc_f(float f) {
    unsigned u = __float_as_uint(f);
    return (u & 0x80000000u) ? ~u : (u | 0x80000000u);
}
__device__ __forceinline__ float dec_f(unsigned e) {
    unsigned u = (e & 0x80000000u) ? (e & 0x7fffffffu) : ~e;
    return __uint_as_float(u);
}
#define ENC_NEG_INF 0x007fffffu   // enc(-inf)

// Twiddle table: tw[k] = exp(-2*pi*i*k/NFFT), k in [0, 1024).
#define TWN 1024
__device__ __forceinline__ void build_twiddles(float2* tw) {
    for (int k = threadIdx.x; k < TWN; k += TFT) {
        float s, c;
        sincospif(-(float)k * (1.0f / (float)HALF), &s, &c);  // angle = -pi*k/4096
        tw[k] = make_float2(c, s);
    }
}

// 8-point DFT core: given x[0..7], produce the 8 pre-twiddle outputs y[0..7]
// (y[m] gets multiplied by w1^m by the caller). INV toggles conjugation.
template <bool INV>
__device__ __forceinline__ void bfly8(const float2* x, float2* y) {
    const float RS2 = 0.70710678118654752f;
    float2 t0 = caddf(x[0], x[4]), t1 = csubf(x[0], x[4]);
    float2 t2 = caddf(x[2], x[6]), t3 = csubf(x[2], x[6]);
    float2 t4 = caddf(x[1], x[5]), t5 = csubf(x[1], x[5]);
    float2 t6 = caddf(x[3], x[7]), t7 = csubf(x[3], x[7]);
    float2 r3 = INV ? make_float2(-t3.y, t3.x) : make_float2(t3.y, -t3.x);
    float2 r7 = INV ? make_float2(-t7.y, t7.x) : make_float2(t7.y, -t7.x);
    float2 E0 = caddf(t0, t2), E2 = csubf(t0, t2);
    float2 E1 = caddf(t1, r3), E3 = csubf(t1, r3);
    float2 O0 = caddf(t4, t6), O2 = csubf(t4, t6);
    float2 O1 = caddf(t5, r7), O3 = csubf(t5, r7);
    float2 o1 = INV ? make_float2(RS2 * (O1.x - O1.y), RS2 * (O1.x + O1.y))
                    : make_float2(RS2 * (O1.x + O1.y), RS2 * (O1.y - O1.x));
    float2 o2 = INV ? make_float2(-O2.y, O2.x) : make_float2(O2.y, -O2.x);
    float2 o3 = INV ? make_float2(-RS2 * (O3.x + O3.y), RS2 * (O3.x - O3.y))
                    : make_float2(RS2 * (O3.y - O3.x), -RS2 * (O3.x + O3.y));
    y[0] = caddf(E0, O0); y[1] = caddf(E1, o1);
    y[2] = caddf(E2, o2); y[3] = caddf(E3, o3);
    y[4] = csubf(E0, O0); y[5] = csubf(E1, o1);
    y[6] = csubf(E2, o2); y[7] = csubf(E3, o3);
}

// ---------------------------------------------------------------------------
// In-place shared-memory forward Stockham FFT, 8192 points, 512 threads.
// 4 radix-8 stages + 1 trivial radix-2 (used by fwd kernel only).
// ---------------------------------------------------------------------------
__device__ void block_fft_fwd(float2* buf, const float2* __restrict__ tw) {
    #pragma unroll
    for (int ls = 0; ls <= 9; ls += 3) {       // s = 1, 8, 64, 512
        float2 X[2][8];
        #pragma unroll
        for (int h = 0; h < 2; h++) {
            int u = threadIdx.x + h * TFT;
            #pragma unroll
            for (int k = 0; k < 8; k++)
                X[h][k] = buf[IX(u + k * 1024)];
        }
        __syncthreads();
        #pragma unroll
        for (int h = 0; h < 2; h++) {
            int u = threadIdx.x + h * TFT;
            int p = u >> ls;
            float2 y[8];
            bfly8<false>(X[h], y);
            float2 w1 = tw[p << ls];
            float2 w2 = cmulf(w1, w1);
            float2 w3 = cmulf(w2, w1);
            float2 w4 = cmulf(w2, w2);
            int s = 1 << ls;
            int j = u + 7 * (p << ls);
            buf[IX(j)]         = y[0];
            buf[IX(j + s)]     = cmulf(y[1], w1);
            buf[IX(j + 2 * s)] = cmulf(y[2], w2);
            buf[IX(j + 3 * s)] = cmulf(y[3], w3);
            buf[IX(j + 4 * s)] = cmulf(y[4], w4);
            buf[IX(j + 5 * s)] = cmulf(y[5], cmulf(w4, w1));
            buf[IX(j + 6 * s)] = cmulf(y[6], cmulf(w4, w2));
            buf[IX(j + 7 * s)] = cmulf(y[7], cmulf(w4, w3));
        }
        __syncthreads();
    }
    // final radix-2, twiddle 1; same-thread read/write -> in-place safe
    #pragma unroll
    for (int it = 0; it < (NFFT / 2) / TFT; it++) {
        int t = it * TFT + threadIdx.x;
        float2 a = buf[IX(t)];
        float2 b = buf[IX(t + NFFT / 2)];
        buf[IX(t)]            = caddf(a, b);
        buf[IX(t + NFFT / 2)] = csubf(a, b);
    }
    __syncthreads();
}

// ---------------------------------------------------------------------------
// Kernel 1: forward FFT of packed mic pairs.
// ---------------------------------------------------------------------------
__global__ __launch_bounds__(TFT, 2)
void fwd_fft_kernel(const float* __restrict__ signal) {
    extern __shared__ float2 sm[];
    float2* buf = sm;
    float2* tw  = sm + NFFT;

    if (blockIdx.x == 0 && threadIdx.x < BKC)
        g_maxenc[threadIdx.x] = ENC_NEG_INF;

    build_twiddles(tw);

    int g  = blockIdx.x;
    int bk = g >> 1;
    int h  = g & 1;
    const float* s0 = signal + ((size_t)bk * MC + 2 * h) * NFFT;
    const float* s1 = s0 + NFFT;

    for (int i = threadIdx.x; i < NFFT; i += TFT)
        buf[IX(i)] = make_float2(s0[i], s1[i]);
    __syncthreads();

    block_fft_fwd(buf, tw);

    float2* out = &g_spec[(size_t)g * NFFT];
    for (int i = threadIdx.x; i < NFFT; i += TFT)
        out[i] = buf[IX(i)];
}

// ---------------------------------------------------------------------------
// Kernel 2: cross-spectra + PHAT + PRUNED packed inverse FFT.
// 8 x 1024-pt sub-IFFTs (3 radix-8 stages), then recombination over only
// the 896 needed lags (final radix-2 folded in). Block g: bk=g/3, pp=g%3.
// ---------------------------------------------------------------------------
template <int IA, int JA, int IB, int JB>
__device__ void build_phat_packed(const float2* __restrict__ Za,
                                  const float2* __restrict__ Zb,
                                  float2* __restrict__ w) {
    for (int f = threadIdx.x; f < NFFT; f += TFT) {
        int fr = (NFFT - f) & (NFFT - 1);
        float2 za  = Za[f],  zar = Za[fr];
        float2 zb  = Zb[f],  zbr = Zb[fr];
        float2 X[4];
        X[0] = make_float2(0.5f * (za.x + zar.x),  0.5f * (za.y - zar.y));
        X[1] = make_float2(0.5f * (za.y + zar.y), -0.5f * (za.x - zar.x));
        X[2] = make_float2(0.5f * (zb.x + zbr.x),  0.5f * (zb.y - zbr.y));
        X[3] = make_float2(0.5f * (zb.y + zbr.y), -0.5f * (zb.x - zbr.x));

        float2 pa, pb;
        {
            float2 xi = X[IA], xj = X[JA];
            float2 c = make_float2(xi.x * xj.x + xi.y * xj.y,
                                   xi.y * xj.x - xi.x * xj.y);   // Xi * conj(Xj)
            float mag = sqrtf(c.x * c.x + c.y * c.y);
            float inv = 1.0f / fmaxf(mag, 1e-9f);
            pa = make_float2(c.x * inv, c.y * inv);
        }
        {
            float2 xi = X[IB], xj = X[JB];
            float2 c = make_float2(xi.x * xj.x + xi.y * xj.y,
                                   xi.y * xj.x - xi.x * xj.y);
            float mag = sqrtf(c.x * c.x + c.y * c.y);
            float inv = 1.0f / fmaxf(mag, 1e-9f);
            pb = make_float2(c.x * inv, c.y * inv);
        }
        w[IX(f)] = make_float2(pa.x - pb.y, pa.y + pb.x);
    }
}

__global__ __launch_bounds__(TFT, 2)
void cross_ifft_kernel() {
    extern __shared__ float2 sm[];
    float2* buf = sm;          // 8192 float2: W, then sub-FFT workspace
    float2* tw  = sm + NFFT;

    build_twiddles(tw);

    int g  = blockIdx.x;
    int bk = g / 3;
    int pp = g - 3 * bk;

    const float2* Za = &g_spec[(size_t)(bk * 2 + 0) * NFFT];
    const float2* Zb = &g_spec[(size_t)(bk * 2 + 1) * NFFT];

    if      (pp == 0) build_phat_packed<0, 1, 0, 2>(Za, Zb, buf);
    else if (pp == 1) build_phat_packed<0, 3, 1, 2>(Za, Zb, buf);
    else              build_phat_packed<1, 3, 2, 3>(Za, Zb, buf);
    __syncthreads();

    // ---- 8 x 1024-pt inverse sub-FFTs (unnormalized), 3 radix-8 stages ----
    // Sub-FFT b input: W[b + 8*f2]; layout after stage A: buf[b*1024 + idx].
    // Stage A: ls=0 (gather), Stage B: ls=3, Stage C: ls=6.
    // Inverse twiddle: conj(tw[8 * (p<<ls)]) since tw is exp(-2pi i k/8192).
    {
        // Stage A
        float2 X[2][8];
        #pragma unroll
        for (int h = 0; h < 2; h++) {
            int gi = threadIdx.x + h * TFT;     // [0, 1024)
            int b  = gi >> 7, t = gi & 127;
            #pragma unroll
            for (int k = 0; k < 8; k++)
                X[h][k] = buf[IX(b + 8 * t + 1024 * k)];
        }
        __syncthreads();
        #pragma unroll
        for (int h = 0; h < 2; h++) {
            int gi = threadIdx.x + h * TFT;
            int b  = gi >> 7, t = gi & 127;
            float2 y[8];
            bfly8<true>(X[h], y);
            float2 w1 = tw[8 * t];  w1.y = -w1.y;     // exp(+2pi i t/1024)
            float2 w2 = cmulf(w1, w1);
            float2 w3 = cmulf(w2, w1);
            float2 w4 = cmulf(w2, w2);
            int base = b * 1024;
            int j = 8 * t;
            buf[base + IX(j)]     = y[0];
            buf[base + IX(j + 1)] = cmulf(y[1], w1);
            buf[base + IX(j + 2)] = cmulf(y[2], w2);
            buf[base + IX(j + 3)] = cmulf(y[3], w3);
            buf[base + IX(j + 4)] = cmulf(y[4], w4);
            buf[base + IX(j + 5)] = cmulf(y[5], cmulf(w4, w1));
            buf[base + IX(j + 6)] = cmulf(y[6], cmulf(w4, w2));
            buf[base + IX(j + 7)] = cmulf(y[7], cmulf(w4, w3));
        }
        __syncthreads();
    }
    #pragma unroll
    for (int ls = 3; ls <= 6; ls += 3) {   // Stages B (ls=3) and C (ls=6)
        float2 X[2][8];
        #pragma unroll
        for (int h = 0; h < 2; h++) {
            int gi = threadIdx.x + h * TFT;
            int b  = gi >> 7, u = gi & 127;
            int base = b * 1024;
            #pragma unroll
            for (int k = 0; k < 8; k++)
                X[h][k] = buf[base + IX(u + 128 * k)];
        }
        __syncthreads();
        #pragma unroll
        for (int h = 0; h < 2; h++) {
            int gi = threadIdx.x + h * TFT;
            int b  = gi >> 7, u = gi & 127;
            int p  = u >> ls;
            float2 y[8];
            bfly8<true>(X[h], y);
            float2 w1 = tw[8 * (p << ls)];  w1.y = -w1.y;
            float2 w2 = cmulf(w1, w1);
            float2 w3 = cmulf(w2, w1);
            float2 w4 = cmulf(w2, w2);
            int s = 1 << ls;
            int base = b * 1024;
            int j = u + 7 * (p << ls);
            buf[base + IX(j)]         = y[0];
            buf[base + IX(j + s)]     = cmulf(y[1], w1);
            buf[base + IX(j + 2 * s)] = cmulf(y[2], w2);
            buf[base + IX(j + 3 * s)] = cmulf(y[3], w3);
            buf[base + IX(j + 4 * s)] = cmulf(y[4], w4);
            buf[base + IX(j + 5 * s)] = cmulf(y[5], cmulf(w4, w1));
            buf[base + IX(j + 6 * s)] = cmulf(y[6], cmulf(w4, w2));
            buf[base + IX(j + 7 * s)] = cmulf(y[7], cmulf(w4, w3));
        }
        __syncthreads();
    }

    // ---- recombination over the 896 needed lags ----
    // cc[idx] = (1/N) * sum_{f1=0}^{7} e^{+2pi i f1 (idx-4096)/8192} * Z_{f1}[(idx-4096)&1023]
    // with final radix-2 folded: Z[zi] = S[zi&511] + sgn * S[(zi&511)+512], sgn=+1 if zi<512.
    const float invN = 1.0f / (float)NFFT;
    int pA = 2 * pp, pB = pA + 1;
    float* CA = &g_cc[((size_t)bk * PC + pA) * CCN];
    float* CB = &g_cc[((size_t)bk * PC + pB) * CCN];
    for (int o = threadIdx.x; o < CCN; o += TFT) {
        int idx = CCLO + o;
        int ms  = idx - 4096;                 // signed lag in [-448, 447]
        int zi  = ms & 1023;
        int zl  = zi & 511;
        float sgn = (zi < 512) ? 1.0f : -1.0f;
        int am  = ms < 0 ? -ms : ms;
        float2 wb = tw[am];                   // exp(-2pi i |ms|/8192)
        if (ms > 0) wb.y = -wb.y;             // -> exp(+2pi i ms/8192)

        int i0 = IX(zl), i1 = IX(zl + 512);
        float2 s0 = buf[i0], s1 = buf[i1];
        float2 acc = make_float2(s0.x + sgn * s1.x, s0.y + sgn * s1.y);
        float2 wc = wb;
        #pragma unroll
        for (int f1 = 1; f1 < 8; f1++) {
            float2 a0 = buf[f1 * 1024 + i0];
            float2 a1 = buf[f1 * 1024 + i1];
            float2 z  = make_float2(a0.x + sgn * a1.x, a0.y + sgn * a1.y);
            acc = caddf(acc, cmulf(z, wc));
            wc = cmulf(wc, wb);
        }
        CA[o] = acc.x * invN;
        CB[o] = acc.y * invN;
    }
}

// ---------------------------------------------------------------------------
// Kernel 3: SRP grid accumulation + per-(b,k) max via atomicMax.
// Delay path mimics XLA:CPU partial-fast-math codegen — DO NOT CHANGE:
//   dist = sqrt( fma(dx, dx, dy*dy) ); x = (d_i-d_j)*fl(16000/343);
//   delay = roundeven(x) + N/2
// cc reads use the compact window (clamp never binds for reachable delays).
// ---------------------------------------------------------------------------
__global__ __launch_bounds__(GD)
void grid_kernel(const float* __restrict__ mic,
                 const float* __restrict__ room,
                 float* __restrict__ out) {
    __shared__ float wred[4];
    int bid = blockIdx.x;
    int bk  = bid >> 7;          // /128
    int gi  = bid & 127;
    int b   = bk >> 2;           // /K
    int gj  = threadIdx.x;

    const float step = 1.0f / 127.0f;
    float tx = __fmul_rn((float)gi, step);
    float ty = __fmul_rn((float)gj, step);
    float gx = __fmul_rn(__ldg(&room[b * 3 + 0]), tx);
    float gy = __fmul_rn(__ldg(&room[b * 3 + 1]), ty);

    float d[4];
    #pragma unroll
    for (int m = 0; m < 4; m++) {
        float mx = __ldg(&mic[((size_t)bk * MC + m) * 3 + 0]);
        float my = __ldg(&mic[((size_t)bk * MC + m) * 3 + 1]);
        float dx = __fsub_rn(gx, mx);
        float dy = __fsub_rn(gy, my);
        float dy2 = __fmul_rn(dy, dy);
        d[m] = sqrtf(__fmaf_rn(dx, dx, dy2));   // LLVM contraction order
    }

    const float SCALE = __fdiv_rn(16000.0f, 343.0f);  // fl(16000/343)

    const int ii[PC] = {0, 0, 0, 1, 1, 2};
    const int jj[PC] = {1, 2, 3, 2, 3, 3};
    float acc = 0.0f;
    #pragma unroll
    for (int p = 0; p < PC; p++) {
        float x     = __fmul_rn(__fsub_rn(d[ii[p]], d[jj[p]]), SCALE);
        int   delay = (int)rintf(x) + HALF;                   // half-even
        const float* C = &g_cc[((size_t)bk * PC + p) * CCN];
        int base = delay - 5;                                 // offs = -5..+4
        float v = 0.0f;
        #pragma unroll
        for (int o = 0; o < 10; o++) {
            int id = min(max(base + o, CCLO), CCLO + CCN - 1);
            v += __ldg(&C[id - CCLO]);
        }
        acc += v;
    }
    out[(size_t)bk * (GD * GD) + gi * GD + gj] = acc;

    // block max -> atomicMax (order-independent -> deterministic)
    float mx = acc;
    #pragma unroll
    for (int o = 16; o; o >>= 1)
        mx = fmaxf(mx, __shfl_xor_sync(0xffffffffu, mx, o));
    if ((threadIdx.x & 31) == 0) wred[threadIdx.x >> 5] = mx;
    __syncthreads();
    if (threadIdx.x == 0) {
        mx = fmaxf(fmaxf(wred[0], wred[1]), fmaxf(wred[2], wred[3]));
        atomicMax(&g_maxenc[bk], enc_f(mx));
    }
}

// ---------------------------------------------------------------------------
// Kernel 4: wide vectorized divide by per-(b,k) max (measured-best shape).
// ---------------------------------------------------------------------------
__global__ __launch_bounds__(256)
void divide_kernel(float* __restrict__ out) {
    int i  = blockIdx.x * 256 + threadIdx.x;   // float4 index, [0, 256K)
    int bk = i >> 12;                          // 4096 float4 per (b,k)
    float m = dec_f(g_maxenc[bk]);
    float4 v = reinterpret_cast<float4*>(out)[i];
    v.x = __fdiv_rn(v.x, m);
    v.y = __fdiv_rn(v.y, m);
    v.z = __fdiv_rn(v.z, m);
    v.w = __fdiv_rn(v.w, m);
    reinterpret_cast<float4*>(out)[i] = v;
}

// ---------------------------------------------------------------------------
extern "C" void kernel_launch(void* const* d_in, const int* in_sizes, int n_in,
                              void* d_out, int out_size) {
    const float* signal = (const float*)d_in[0];  // (B,K,M,N)
    const float* mic    = (const float*)d_in[1];  // (B,K,M,3)
    const float* room   = (const float*)d_in[2];  // (B,3)
    float* out = (float*)d_out;                   // (B,K,G*G)

    const int smem = (NFFT + TWN) * (int)sizeof(float2);  // 72 KB
    cudaFuncSetAttribute(fwd_fft_kernel,    cudaFuncAttributeMaxDynamicSharedMemorySize, smem);
    cudaFuncSetAttribute(cross_ifft_kernel, cudaFuncAttributeMaxDynamicSharedMemorySize, smem);

    fwd_fft_kernel<<<BKC * 2, TFT, smem>>>(signal);
    cross_ifft_kernel<<<BKC * 3, TFT, smem>>>();
    grid_kernel<<<BKC * GD, GD>>>(mic, room, out);
    divide_kernel<<<(BKC * GD * GD / 4) / 256, 256>>>(out);
}

// round 10
// speedup vs baseline: 1.4631x; 1.2854x over previous
#include <cuda_runtime.h>
#include <cstdint>

// Problem constants
#define NFFT 8192
#define HALF 4096
#define GD   128
#define BC   16
#define KC   4
#define MC   4
#define PC   6
#define BKC  (BC*KC)   // 64
#define TFT  512       // threads per FFT block

// Compact cc window: delays live in 4096 +/- 396, band +/-5 -> [3695, 4497).
// Store [3648, 4544) = 896 lags (margin 48 each side). Prefix rows: 897.
#define CCLO 3648
#define CCN  896
#define CCS  897

// Smem swizzle: XOR (bits[3:6) ^ bits[6:9)) into bits[0:3).
// Base-preserving for any base that is a multiple of 1024.
#define IX(i) ((i) ^ (((((i) >> 3) ^ ((i) >> 6))) & 7))

// Scratch (device globals — no allocation allowed)
__device__ float2   g_spec[BKC * 2 * NFFT];      // packed forward spectra, 8.4 MB
__device__ float    g_cc[BKC * PC * CCS];        // per-pair cc prefix sums, 1.37 MB
__device__ unsigned g_maxenc[BKC];               // per-(b,k) max, ordered-uint encoded

__device__ __forceinline__ float2 cmulf(float2 a, float2 b) {
    return make_float2(a.x * b.x - a.y * b.y, a.x * b.y + a.y * b.x);
}
__device__ __forceinline__ float2 caddf(float2 a, float2 b) { return make_float2(a.x + b.x, a.y + b.y); }
__device__ __forceinline__ float2 csubf(float2 a, float2 b) { return make_float2(a.x - b.x, a.y - b.y); }

// ordered-uint encoding for float atomicMax (handles negatives)
__device__ __forceinline__ unsigned enc_f(float f) {
    unsigned u = __float_as_uint(f);
    return (u & 0x80000000u) ? ~u : (u | 0x80000000u);
}
__device__ __forceinline__ float dec_f(unsigned e) {
    unsigned u = (e & 0x80000000u) ? (e & 0x7fffffffu) : ~e;
    return __uint_as_float(u);
}
#define ENC_NEG_INF 0x007fffffu   // enc(-inf)

// Twiddle table: tw[k] = exp(-2*pi*i*k/NFFT), k in [0, 1024).
#define TWN 1024
__device__ __forceinline__ void build_twiddles(float2* tw) {
    for (int k = threadIdx.x; k < TWN; k += TFT) {
        float s, c;
        sincospif(-(float)k * (1.0f / (float)HALF), &s, &c);  // angle = -pi*k/4096
        tw[k] = make_float2(c, s);
    }
}

// 8-point DFT core. INV toggles conjugation.
template <bool INV>
__device__ __forceinline__ void bfly8(const float2* x, float2* y) {
    const float RS2 = 0.70710678118654752f;
    float2 t0 = caddf(x[0], x[4]), t1 = csubf(x[0], x[4]);
    float2 t2 = caddf(x[2], x[6]), t3 = csubf(x[2], x[6]);
    float2 t4 = caddf(x[1], x[5]), t5 = csubf(x[1], x[5]);
    float2 t6 = caddf(x[3], x[7]), t7 = csubf(x[3], x[7]);
    float2 r3 = INV ? make_float2(-t3.y, t3.x) : make_float2(t3.y, -t3.x);
    float2 r7 = INV ? make_float2(-t7.y, t7.x) : make_float2(t7.y, -t7.x);
    float2 E0 = caddf(t0, t2), E2 = csubf(t0, t2);
    float2 E1 = caddf(t1, r3), E3 = csubf(t1, r3);
    float2 O0 = caddf(t4, t6), O2 = csubf(t4, t6);
    float2 O1 = caddf(t5, r7), O3 = csubf(t5, r7);
    float2 o1 = INV ? make_float2(RS2 * (O1.x - O1.y), RS2 * (O1.x + O1.y))
                    : make_float2(RS2 * (O1.x + O1.y), RS2 * (O1.y - O1.x));
    float2 o2 = INV ? make_float2(-O2.y, O2.x) : make_float2(O2.y, -O2.x);
    float2 o3 = INV ? make_float2(-RS2 * (O3.x + O3.y), RS2 * (O3.x - O3.y))
                    : make_float2(RS2 * (O3.y - O3.x), -RS2 * (O3.x + O3.y));
    y[0] = caddf(E0, O0); y[1] = caddf(E1, o1);
    y[2] = caddf(E2, o2); y[3] = caddf(E3, o3);
    y[4] = csubf(E0, O0); y[5] = csubf(E1, o1);
    y[6] = csubf(E2, o2); y[7] = csubf(E3, o3);
}

// ---------------------------------------------------------------------------
// In-place forward Stockham FFT stages: 4 radix-8 stages (the final radix-2
// is folded into the caller's gmem store).
// ---------------------------------------------------------------------------
__device__ void block_fft_fwd_stages(float2* buf, const float2* __restrict__ tw) {
    #pragma unroll
    for (int ls = 0; ls <= 9; ls += 3) {       // s = 1, 8, 64, 512
        float2 X[2][8];
        #pragma unroll
        for (int h = 0; h < 2; h++) {
            int u = threadIdx.x + h * TFT;
            #pragma unroll
            for (int k = 0; k < 8; k++)
                X[h][k] = buf[IX(u + k * 1024)];
        }
        __syncthreads();
        #pragma unroll
        for (int h = 0; h < 2; h++) {
            int u = threadIdx.x + h * TFT;
            int p = u >> ls;
            float2 y[8];
            bfly8<false>(X[h], y);
            float2 w1 = tw[p << ls];
            float2 w2 = cmulf(w1, w1);
            float2 w3 = cmulf(w2, w1);
            float2 w4 = cmulf(w2, w2);
            int s = 1 << ls;
            int j = u + 7 * (p << ls);
            buf[IX(j)]         = y[0];
            buf[IX(j + s)]     = cmulf(y[1], w1);
            buf[IX(j + 2 * s)] = cmulf(y[2], w2);
            buf[IX(j + 3 * s)] = cmulf(y[3], w3);
            buf[IX(j + 4 * s)] = cmulf(y[4], w4);
            buf[IX(j + 5 * s)] = cmulf(y[5], cmulf(w4, w1));
            buf[IX(j + 6 * s)] = cmulf(y[6], cmulf(w4, w2));
            buf[IX(j + 7 * s)] = cmulf(y[7], cmulf(w4, w3));
        }
        __syncthreads();
    }
}

// ---------------------------------------------------------------------------
// Kernel 1: forward FFT of packed mic pairs; final radix-2 folded into store.
// ---------------------------------------------------------------------------
__global__ __launch_bounds__(TFT, 2)
void fwd_fft_kernel(const float* __restrict__ signal) {
    extern __shared__ float2 sm[];
    float2* buf = sm;
    float2* tw  = sm + NFFT;

    if (blockIdx.x == 0 && threadIdx.x < BKC)
        g_maxenc[threadIdx.x] = ENC_NEG_INF;

    build_twiddles(tw);

    int g  = blockIdx.x;
    int bk = g >> 1;
    int h  = g & 1;
    const float* s0 = signal + ((size_t)bk * MC + 2 * h) * NFFT;
    const float* s1 = s0 + NFFT;

    for (int i = threadIdx.x; i < NFFT; i += TFT)
        buf[IX(i)] = make_float2(s0[i], s1[i]);
    __syncthreads();

    block_fft_fwd_stages(buf, tw);

    // final radix-2 (s=4096, twiddle=1) folded into the gmem store
    float2* out = &g_spec[(size_t)g * NFFT];
    for (int i = threadIdx.x; i < NFFT / 2; i += TFT) {
        float2 a = buf[IX(i)];
        float2 b = buf[IX(i + NFFT / 2)];
        out[i]            = caddf(a, b);
        out[i + NFFT / 2] = csubf(a, b);
    }
}

// ---------------------------------------------------------------------------
// Kernel 2: cross-spectra + PHAT + pruned packed inverse FFT + recombination
// + in-block prefix scan of the compact cc window.
// Block g in [0,192): bk = g/3, pp = g%3; pairs 2pp and 2pp+1.
// ---------------------------------------------------------------------------
template <int IA, int JA, int IB, int JB>
__device__ void build_phat_packed(const float2* __restrict__ Za,
                                  const float2* __restrict__ Zb,
                                  float2* __restrict__ w) {
    for (int f = threadIdx.x; f < NFFT; f += TFT) {
        int fr = (NFFT - f) & (NFFT - 1);
        float2 za  = Za[f],  zar = Za[fr];
        float2 zb  = Zb[f],  zbr = Zb[fr];
        float2 X[4];
        X[0] = make_float2(0.5f * (za.x + zar.x),  0.5f * (za.y - zar.y));
        X[1] = make_float2(0.5f * (za.y + zar.y), -0.5f * (za.x - zar.x));
        X[2] = make_float2(0.5f * (zb.x + zbr.x),  0.5f * (zb.y - zbr.y));
        X[3] = make_float2(0.5f * (zb.y + zbr.y), -0.5f * (zb.x - zbr.x));

        float2 pa, pb;
        {
            float2 xi = X[IA], xj = X[JA];
            float2 c = make_float2(xi.x * xj.x + xi.y * xj.y,
                                   xi.y * xj.x - xi.x * xj.y);   // Xi * conj(Xj)
            float mag = sqrtf(c.x * c.x + c.y * c.y);
            float inv = 1.0f / fmaxf(mag, 1e-9f);
            pa = make_float2(c.x * inv, c.y * inv);
        }
        {
            float2 xi = X[IB], xj = X[JB];
            float2 c = make_float2(xi.x * xj.x + xi.y * xj.y,
                                   xi.y * xj.x - xi.x * xj.y);
            float mag = sqrtf(c.x * c.x + c.y * c.y);
            float inv = 1.0f / fmaxf(mag, 1e-9f);
            pb = make_float2(c.x * inv, c.y * inv);
        }
        w[IX(f)] = make_float2(pa.x - pb.y, pa.y + pb.x);
    }
}

__global__ __launch_bounds__(TFT, 2)
void cross_ifft_kernel() {
    extern __shared__ float2 sm[];
    float2* buf = sm;          // 8192 float2: W, then sub-FFT workspace
    float2* tw  = sm + NFFT;
    float*  sA  = (float*)(sm + NFFT + TWN);   // 896 cc values pair A
    float*  sB  = sA + CCN;                    // 896 cc values pair B

    build_twiddles(tw);

    int g  = blockIdx.x;
    int bk = g / 3;
    int pp = g - 3 * bk;

    const float2* Za = &g_spec[(size_t)(bk * 2 + 0) * NFFT];
    const float2* Zb = &g_spec[(size_t)(bk * 2 + 1) * NFFT];

    if      (pp == 0) build_phat_packed<0, 1, 0, 2>(Za, Zb, buf);
    else if (pp == 1) build_phat_packed<0, 3, 1, 2>(Za, Zb, buf);
    else              build_phat_packed<1, 3, 2, 3>(Za, Zb, buf);
    __syncthreads();

    // ---- 8 x 1024-pt inverse sub-FFTs (unnormalized), 3 radix-8 stages ----
    {
        // Stage A (gather W[b + 8*f2])
        float2 X[2][8];
        #pragma unroll
        for (int h = 0; h < 2; h++) {
            int gi = threadIdx.x + h * TFT;     // [0, 1024)
            int b  = gi >> 7, t = gi & 127;
            #pragma unroll
            for (int k = 0; k < 8; k++)
                X[h][k] = buf[IX(b + 8 * t + 1024 * k)];
        }
        __syncthreads();
        #pragma unroll
        for (int h = 0; h < 2; h++) {
            int gi = threadIdx.x + h * TFT;
            int b  = gi >> 7, t = gi & 127;
            float2 y[8];
            bfly8<true>(X[h], y);
            float2 w1 = tw[8 * t];  w1.y = -w1.y;     // exp(+2pi i t/1024)
            float2 w2 = cmulf(w1, w1);
            float2 w3 = cmulf(w2, w1);
            float2 w4 = cmulf(w2, w2);
            int base = b * 1024;
            int j = 8 * t;
            buf[base + IX(j)]     = y[0];
            buf[base + IX(j + 1)] = cmulf(y[1], w1);
            buf[base + IX(j + 2)] = cmulf(y[2], w2);
            buf[base + IX(j + 3)] = cmulf(y[3], w3);
            buf[base + IX(j + 4)] = cmulf(y[4], w4);
            buf[base + IX(j + 5)] = cmulf(y[5], cmulf(w4, w1));
            buf[base + IX(j + 6)] = cmulf(y[6], cmulf(w4, w2));
            buf[base + IX(j + 7)] = cmulf(y[7], cmulf(w4, w3));
        }
        __syncthreads();
    }
    #pragma unroll
    for (int ls = 3; ls <= 6; ls += 3) {   // Stages B (ls=3) and C (ls=6)
        float2 X[2][8];
        #pragma unroll
        for (int h = 0; h < 2; h++) {
            int gi = threadIdx.x + h * TFT;
            int b  = gi >> 7, u = gi & 127;
            int base = b * 1024;
            #pragma unroll
            for (int k = 0; k < 8; k++)
                X[h][k] = buf[base + IX(u + 128 * k)];
        }
        __syncthreads();
        #pragma unroll
        for (int h = 0; h < 2; h++) {
            int gi = threadIdx.x + h * TFT;
            int b  = gi >> 7, u = gi & 127;
            int p  = u >> ls;
            float2 y[8];
            bfly8<true>(X[h], y);
            float2 w1 = tw[8 * (p << ls)];  w1.y = -w1.y;
            float2 w2 = cmulf(w1, w1);
            float2 w3 = cmulf(w2, w1);
            float2 w4 = cmulf(w2, w2);
            int s = 1 << ls;
            int base = b * 1024;
            int j = u + 7 * (p << ls);
            buf[base + IX(j)]         = y[0];
            buf[base + IX(j + s)]     = cmulf(y[1], w1);
            buf[base + IX(j + 2 * s)] = cmulf(y[2], w2);
            buf[base + IX(j + 3 * s)] = cmulf(y[3], w3);
            buf[base + IX(j + 4 * s)] = cmulf(y[4], w4);
            buf[base + IX(j + 5 * s)] = cmulf(y[5], cmulf(w4, w1));
            buf[base + IX(j + 6 * s)] = cmulf(y[6], cmulf(w4, w2));
            buf[base + IX(j + 7 * s)] = cmulf(y[7], cmulf(w4, w3));
        }
        __syncthreads();
    }

    // ---- recombination over the 896 needed lags -> smem ----
    const float invN = 1.0f / (float)NFFT;
    for (int o = threadIdx.x; o < CCN; o += TFT) {
        int idx = CCLO + o;
        int ms  = idx - 4096;                 // signed lag in [-448, 447]
        int zi  = ms & 1023;
        int zl  = zi & 511;
        float sgn = (zi < 512) ? 1.0f : -1.0f;
        int am  = ms < 0 ? -ms : ms;
        float2 wb = tw[am];                   // exp(-2pi i |ms|/8192)
        if (ms > 0) wb.y = -wb.y;             // -> exp(+2pi i ms/8192)

        int i0 = IX(zl), i1 = IX(zl + 512);
        float2 s0 = buf[i0], s1 = buf[i1];
        float2 acc = make_float2(s0.x + sgn * s1.x, s0.y + sgn * s1.y);
        float2 wc = wb;
        #pragma unroll
        for (int f1 = 1; f1 < 8; f1++) {
            float2 a0 = buf[f1 * 1024 + i0];
            float2 a1 = buf[f1 * 1024 + i1];
            float2 z  = make_float2(a0.x + sgn * a1.x, a0.y + sgn * a1.y);
            acc = caddf(acc, cmulf(z, wc));
            wc = cmulf(wc, wb);
        }
        sA[o] = acc.x * invN;
        sB[o] = acc.y * invN;
    }
    __syncthreads();

    // ---- exclusive prefix scan of each 896-row (warp 0 -> A, warp 1 -> B) ---
    // Deterministic fixed order. S[0]=0, S[o+1]=sum(cc[0..o]).
    int wid  = threadIdx.x >> 5;
    int lane = threadIdx.x & 31;
    if (wid < 2) {
        const float* Ssrc = (wid == 0) ? sA : sB;
        float* Gdst = &g_cc[((size_t)bk * PC + 2 * pp + wid) * CCS];
        float carry = 0.0f;
        #pragma unroll 4
        for (int c = 0; c < CCN / 32; c++) {
            float v = Ssrc[c * 32 + lane];
            #pragma unroll
            for (int off = 1; off < 32; off <<= 1) {
                float t = __shfl_up_sync(0xffffffffu, v, off);
                if (lane >= off) v += t;
            }
            Gdst[c * 32 + lane + 1] = carry + v;
            carry += __shfl_sync(0xffffffffu, v, 31);
        }
        if (lane == 0) Gdst[0] = 0.0f;
    }
}

// ---------------------------------------------------------------------------
// Kernel 3: SRP grid accumulation via prefix differences (2 loads per pair).
// Delay path mimics XLA:CPU partial-fast-math codegen — DO NOT CHANGE:
//   dist = sqrt( fma(dx, dx, dy*dy) ); x = (d_i-d_j)*fl(16000/343);
//   delay = roundeven(x) + N/2
// Band sum = S[base+10] - S[base], base = delay-5-CCLO (always in range:
// |tdoa*SR| <= 396, window margin 48-5 > 0; safety clamp kept, never binds).
// ---------------------------------------------------------------------------
__global__ __launch_bounds__(GD)
void grid_kernel(const float* __restrict__ mic,
                 const float* __restrict__ room,
                 float* __restrict__ out) {
    __shared__ float wred[4];
    int bid = blockIdx.x;
    int bk  = bid >> 7;          // /128
    int gi  = bid & 127;
    int b   = bk >> 2;           // /K
    int gj  = threadIdx.x;

    const float step = 1.0f / 127.0f;
    float tx = __fmul_rn((float)gi, step);
    float ty = __fmul_rn((float)gj, step);
    float gx = __fmul_rn(__ldg(&room[b * 3 + 0]), tx);
    float gy = __fmul_rn(__ldg(&room[b * 3 + 1]), ty);

    float d[4];
    #pragma unroll
    for (int m = 0; m < 4; m++) {
        float mx = __ldg(&mic[((size_t)bk * MC + m) * 3 + 0]);
        float my = __ldg(&mic[((size_t)bk * MC + m) * 3 + 1]);
        float dx = __fsub_rn(gx, mx);
        float dy = __fsub_rn(gy, my);
        float dy2 = __fmul_rn(dy, dy);
        d[m] = sqrtf(__fmaf_rn(dx, dx, dy2));   // LLVM contraction order
    }

    const float SCALE = __fdiv_rn(16000.0f, 343.0f);  // fl(16000/343)

    const int ii[PC] = {0, 0, 0, 1, 1, 2};
    const int jj[PC] = {1, 2, 3, 2, 3, 3};
    float acc = 0.0f;
    #pragma unroll
    for (int p = 0; p < PC; p++) {
        float x     = __fmul_rn(__fsub_rn(d[ii[p]], d[jj[p]]), SCALE);
        int   delay = (int)rintf(x) + HALF;                   // half-even
        const float* S = &g_cc[((size_t)bk * PC + p) * CCS];
        int base = delay - 5 - CCLO;
        base = min(max(base, 0), CCS - 11);                   // safety, never binds
        acc += __ldg(&S[base + 10]) - __ldg(&S[base]);
    }
    out[(size_t)bk * (GD * GD) + gi * GD + gj] = acc;

    // block max -> atomicMax (order-independent -> deterministic)
    float mx = acc;
    #pragma unroll
    for (int o = 16; o; o >>= 1)
        mx = fmaxf(mx, __shfl_xor_sync(0xffffffffu, mx, o));
    if ((threadIdx.x & 31) == 0) wred[threadIdx.x >> 5] = mx;
    __syncthreads();
    if (threadIdx.x == 0) {
        mx = fmaxf(fmaxf(wred[0], wred[1]), fmaxf(wred[2], wred[3]));
        atomicMax(&g_maxenc[bk], enc_f(mx));
    }
}

// ---------------------------------------------------------------------------
// Kernel 4: wide vectorized divide by per-(b,k) max (measured-best shape).
// ---------------------------------------------------------------------------
__global__ __launch_bounds__(256)
void divide_kernel(float* __restrict__ out) {
    int i  = blockIdx.x * 256 + threadIdx.x;   // float4 index, [0, 256K)
    int bk = i >> 12;                          // 4096 float4 per (b,k)
    float m = dec_f(g_maxenc[bk]);
    float4 v = reinterpret_cast<float4*>(out)[i];
    v.x = __fdiv_rn(v.x, m);
    v.y = __fdiv_rn(v.y, m);
    v.z = __fdiv_rn(v.z, m);
    v.w = __fdiv_rn(v.w, m);
    reinterpret_cast<float4*>(out)[i] = v;
}

// ---------------------------------------------------------------------------
extern "C" void kernel_launch(void* const* d_in, const int* in_sizes, int n_in,
                              void* d_out, int out_size) {
    const float* signal = (const float*)d_in[0];  // (B,K,M,N)
    const float* mic    = (const float*)d_in[1];  // (B,K,M,3)
    const float* room   = (const float*)d_in[2];  // (B,3)
    float* out = (float*)d_out;                   // (B,K,G*G)

    const int smem = (NFFT + TWN) * (int)sizeof(float2) + 2 * CCN * (int)sizeof(float);
    cudaFuncSetAttribute(fwd_fft_kernel,    cudaFuncAttributeMaxDynamicSharedMemorySize, smem);
    cudaFuncSetAttribute(cross_ifft_kernel, cudaFuncAttributeMaxDynamicSharedMemorySize, smem);

    fwd_fft_kernel<<<BKC * 2, TFT, smem>>>(signal);
    cross_ifft_kernel<<<BKC * 3, TFT, smem>>>();
    grid_kernel<<<BKC * GD, GD>>>(mic, room, out);
    divide_kernel<<<(BKC * GD * GD / 4) / 256, 256>>>(out);
}

// round 11
// speedup vs baseline: 1.6650x; 1.1380x over previous
#include <cuda_runtime.h>
#include <cstdint>

// Problem constants
#define NFFT 8192
#define HALF 4096
#define GD   128
#define BC   16
#define KC   4
#define MC   4
#define PC   6
#define BKC  (BC*KC)   // 64
#define TFT  512       // threads per FFT block

// Compact cc window: delays live in 4096 +/- 396, band +/-5 -> [3695, 4497).
// Store [3648, 4544) = 896 lags. Prefix rows: 897.
#define CCLO 3648
#define CCN  896
#define CCS  897

// Smem swizzle: XOR (bits[3:6) ^ bits[6:9)) into bits[0:3).
// Bijective on [0,1024) blocks; base-preserving for multiples of 1024.
#define IX(i) ((i) ^ (((((i) >> 3) ^ ((i) >> 6))) & 7))

// Scratch (device globals — no allocation allowed)
__device__ float2   g_spec[BKC * 2 * NFFT];      // packed forward spectra, 8.4 MB
__device__ float    g_cc[BKC * PC * CCS];        // per-pair cc prefix sums, 1.37 MB
__device__ unsigned g_maxenc[BKC];               // per-(b,k) max, ordered-uint encoded

__device__ __forceinline__ float2 cmulf(float2 a, float2 b) {
    return make_float2(a.x * b.x - a.y * b.y, a.x * b.y + a.y * b.x);
}
__device__ __forceinline__ float2 caddf(float2 a, float2 b) { return make_float2(a.x + b.x, a.y + b.y); }
__device__ __forceinline__ float2 csubf(float2 a, float2 b) { return make_float2(a.x - b.x, a.y - b.y); }

// ordered-uint encoding for float atomicMax (handles negatives)
__device__ __forceinline__ unsigned enc_f(float f) {
    unsigned u = __float_as_uint(f);
    return (u & 0x80000000u) ? ~u : (u | 0x80000000u);
}
__device__ __forceinline__ float dec_f(unsigned e) {
    unsigned u = (e & 0x80000000u) ? (e & 0x7fffffffu) : ~e;
    return __uint_as_float(u);
}
#define ENC_NEG_INF 0x007fffffu   // enc(-inf)

// Twiddle table: tw[k] = exp(-2*pi*i*k/NFFT), k in [0, 512).
// Radix-16 stages index at most tw[511]; recomb |ms| <= 448.
#define TWN 512
__device__ __forceinline__ void build_twiddles(float2* tw) {
    for (int k = threadIdx.x; k < TWN; k += TFT) {
        float s, c;
        sincospif(-(float)k * (1.0f / (float)HALF), &s, &c);  // angle = -pi*k/4096
        tw[k] = make_float2(c, s);
    }
}

// 8-point DFT core (natural-order outputs). INV toggles conjugation.
template <bool INV>
__device__ __forceinline__ void bfly8(const float2* x, float2* y) {
    const float RS2 = 0.70710678118654752f;
    float2 t0 = caddf(x[0], x[4]), t1 = csubf(x[0], x[4]);
    float2 t2 = caddf(x[2], x[6]), t3 = csubf(x[2], x[6]);
    float2 t4 = caddf(x[1], x[5]), t5 = csubf(x[1], x[5]);
    float2 t6 = caddf(x[3], x[7]), t7 = csubf(x[3], x[7]);
    float2 r3 = INV ? make_float2(-t3.y, t3.x) : make_float2(t3.y, -t3.x);
    float2 r7 = INV ? make_float2(-t7.y, t7.x) : make_float2(t7.y, -t7.x);
    float2 E0 = caddf(t0, t2), E2 = csubf(t0, t2);
    float2 E1 = caddf(t1, r3), E3 = csubf(t1, r3);
    float2 O0 = caddf(t4, t6), O2 = csubf(t4, t6);
    float2 O1 = caddf(t5, r7), O3 = csubf(t5, r7);
    float2 o1 = INV ? make_float2(RS2 * (O1.x - O1.y), RS2 * (O1.x + O1.y))
                    : make_float2(RS2 * (O1.x + O1.y), RS2 * (O1.y - O1.x));
    float2 o2 = INV ? make_float2(-O2.y, O2.x) : make_float2(O2.y, -O2.x);
    float2 o3 = INV ? make_float2(-RS2 * (O3.x + O3.y), RS2 * (O3.x - O3.y))
                    : make_float2(RS2 * (O3.y - O3.x), -RS2 * (O3.x + O3.y));
    y[0] = caddf(E0, O0); y[1] = caddf(E1, o1);
    y[2] = caddf(E2, o2); y[3] = caddf(E3, o3);
    y[4] = csubf(E0, O0); y[5] = csubf(E1, o1);
    y[6] = csubf(E2, o2); y[7] = csubf(E3, o3);
}

// ---------------------------------------------------------------------------
// One in-place radix-16 Stockham stage (DIT: two bfly8 + omega16 combine).
// reads  buf[base_r + IX(off_e + str*k)] (evens), off_o (odds), k = 0..7
// writes buf[base_w + IX(j + s*m)] = y[m] * w1^m, m = 0..15
// Contains the read barrier and trailing barrier (in-place safe).
// ---------------------------------------------------------------------------
template <bool INV>
__device__ __forceinline__ void bfly16_stage(float2* buf,
        int base_r, int off_e, int off_o, int str,
        int base_w, int j, int s, float2 w1) {
    float2 e[8], E[8], O[8];
    #pragma unroll
    for (int k = 0; k < 8; k++) e[k] = buf[base_r + IX(off_e + str * k)];
    bfly8<INV>(e, E);
    #pragma unroll
    for (int k = 0; k < 8; k++) e[k] = buf[base_r + IX(off_o + str * k)];
    bfly8<INV>(e, O);
    __syncthreads();

    const float C1 = 0.92387953251128675613f;   // cos(pi/8)
    const float S1 = 0.38268343236508977173f;   // sin(pi/8)
    const float R2 = 0.70710678118654752440f;
    const float RC[8] = {1.0f,  C1,  R2,  S1, 0.0f, -S1, -R2, -C1};
    const float RS[8] = {0.0f,  S1,  R2,  C1, 1.0f,  C1,  R2,  S1};

    float2 w2 = cmulf(w1, w1);
    float2 w4 = cmulf(w2, w2);
    float2 w8 = cmulf(w4, w4);
    float2 wr = make_float2(1.0f, 0.0f);
    #pragma unroll
    for (int r = 0; r < 8; r++) {
        float c = RC[r], sn = RS[r];
        float2 T = INV ? make_float2(O[r].x * c - O[r].y * sn, O[r].y * c + O[r].x * sn)
                       : make_float2(O[r].x * c + O[r].y * sn, O[r].y * c - O[r].x * sn);
        float2 lo = caddf(E[r], T);
        float2 hi = csubf(E[r], T);
        buf[base_w + IX(j + s * r)]       = cmulf(lo, wr);
        buf[base_w + IX(j + s * (r + 8))] = cmulf(hi, cmulf(w8, wr));
        wr = cmulf(wr, w1);
    }
    __syncthreads();
}

// ---------------------------------------------------------------------------
// Kernel 1: forward FFT of packed mic pairs. 3 radix-16 stages + radix-2
// fold into the gmem store. 512 threads = one butterfly per thread per stage.
// ---------------------------------------------------------------------------
__global__ __launch_bounds__(TFT, 2)
void fwd_fft_kernel(const float* __restrict__ signal) {
    extern __shared__ float2 sm[];
    float2* buf = sm;
    float2* tw  = sm + NFFT;

    if (blockIdx.x == 0 && threadIdx.x < BKC)
        g_maxenc[threadIdx.x] = ENC_NEG_INF;

    build_twiddles(tw);

    int g  = blockIdx.x;
    int bk = g >> 1;
    int h  = g & 1;
    const float* s0 = signal + ((size_t)bk * MC + 2 * h) * NFFT;
    const float* s1 = s0 + NFFT;

    for (int i = threadIdx.x; i < NFFT; i += TFT)
        buf[IX(i)] = make_float2(s0[i], s1[i]);
    __syncthreads();

    #pragma unroll
    for (int ls = 0; ls <= 8; ls += 4) {        // s = 1, 16, 256
        int u = threadIdx.x;
        int p = u >> ls;
        bfly16_stage<false>(buf, 0, u, u + 512, 1024,
                            0, u + 15 * (p << ls), 1 << ls, tw[p << ls]);
    }

    // final radix-2 (s=4096, twiddle=1) folded into the gmem store
    float2* out = &g_spec[(size_t)g * NFFT];
    for (int i = threadIdx.x; i < NFFT / 2; i += TFT) {
        float2 a = buf[IX(i)];
        float2 b = buf[IX(i + NFFT / 2)];
        out[i]            = caddf(a, b);
        out[i + NFFT / 2] = csubf(a, b);
    }
}

// ---------------------------------------------------------------------------
// Kernel 2: cross-spectra + PHAT + pruned inverse FFT (8 x 1024-pt sub-IFFTs
// as 2 radix-16 stages; radix-4 + f1-recombination folded into output pass)
// + parallel prefix scan of the compact cc window.
// ---------------------------------------------------------------------------
template <int IA, int JA, int IB, int JB>
__device__ void build_phat_packed(const float2* __restrict__ Za,
                                  const float2* __restrict__ Zb,
                                  float2* __restrict__ w) {
    for (int f = threadIdx.x; f < NFFT; f += TFT) {
        int fr = (NFFT - f) & (NFFT - 1);
        float2 za  = Za[f],  zar = Za[fr];
        float2 zb  = Zb[f],  zbr = Zb[fr];
        float2 X[4];
        X[0] = make_float2(0.5f * (za.x + zar.x),  0.5f * (za.y - zar.y));
        X[1] = make_float2(0.5f * (za.y + zar.y), -0.5f * (za.x - zar.x));
        X[2] = make_float2(0.5f * (zb.x + zbr.x),  0.5f * (zb.y - zbr.y));
        X[3] = make_float2(0.5f * (zb.y + zbr.y), -0.5f * (zb.x - zbr.x));

        float2 pa, pb;
        {
            float2 xi = X[IA], xj = X[JA];
            float2 c = make_float2(xi.x * xj.x + xi.y * xj.y,
                                   xi.y * xj.x - xi.x * xj.y);   // Xi * conj(Xj)
            float inv = rsqrtf(fmaxf(c.x * c.x + c.y * c.y, 1e-18f));
            pa = make_float2(c.x * inv, c.y * inv);
        }
        {
            float2 xi = X[IB], xj = X[JB];
            float2 c = make_float2(xi.x * xj.x + xi.y * xj.y,
                                   xi.y * xj.x - xi.x * xj.y);
            float inv = rsqrtf(fmaxf(c.x * c.x + c.y * c.y, 1e-18f));
            pb = make_float2(c.x * inv, c.y * inv);
        }
        w[IX(f)] = make_float2(pa.x - pb.y, pa.y + pb.x);   // P_A + i*P_B
    }
}

__global__ __launch_bounds__(TFT, 2)
void cross_ifft_kernel() {
    extern __shared__ float2 sm[];
    float2* buf = sm;
    float2* tw  = sm + NFFT;
    float*  sA  = (float*)(sm + NFFT + TWN);   // 896 cc values pair A
    float*  sB  = sA + CCN;                    // 896 cc values pair B
    __shared__ float chtot[16];                // chunk totals for the scan

    build_twiddles(tw);

    int g  = blockIdx.x;
    int bk = g / 3;
    int pp = g - 3 * bk;

    const float2* Za = &g_spec[(size_t)(bk * 2 + 0) * NFFT];
    const float2* Zb = &g_spec[(size_t)(bk * 2 + 1) * NFFT];

    if      (pp == 0) build_phat_packed<0, 1, 0, 2>(Za, Zb, buf);
    else if (pp == 1) build_phat_packed<0, 3, 1, 2>(Za, Zb, buf);
    else              build_phat_packed<1, 3, 2, 3>(Za, Zb, buf);
    __syncthreads();

    // ---- 8 x 1024-pt inverse sub-FFTs: 2 radix-16 stages each ----
    // Sub b input: W[b + 8*f2]. Inverse twiddle = conj of tw entries.
    {   // Stage A: s=1, gather from packed W layout
        int gi = threadIdx.x, b = gi >> 6, t = gi & 63;
        float2 w1 = tw[t << 3];  w1.y = -w1.y;          // W_1024^t conj
        bfly16_stage<true>(buf, 0, b + 8 * t, b + 8 * t + 512, 1024,
                           b * 1024, 16 * t, 1, w1);
    }
    {   // Stage B: s=16, sub-local
        int gi = threadIdx.x, b = gi >> 6, u = gi & 63;
        int p = u >> 4;
        float2 w1 = tw[(p << 4) << 3];  w1.y = -w1.y;
        bfly16_stage<true>(buf, b * 1024, u, u + 64, 128,
                           b * 1024, u + 15 * (p << 4), 16, w1);
    }

    // ---- output pass: fold final radix-4 (p=0, twiddle-free) + recombine
    //      over f1 with exp(+2pi i f1 m/8192), only the 896 needed lags ----
    const float invN = 1.0f / (float)NFFT;
    for (int o = threadIdx.x; o < CCN; o += TFT) {
        int idx = CCLO + o;
        int ms  = idx - 4096;                 // signed lag in [-448, 447]
        int zi  = ms & 1023;
        int u4  = zi & 255;
        int r4  = zi >> 8;
        int am  = ms < 0 ? -ms : ms;
        float2 wb = tw[am];                   // exp(-2pi i |ms|/8192)
        if (ms > 0) wb.y = -wb.y;             // -> exp(+2pi i ms/8192)

        int i0 = IX(u4), i1 = IX(u4 + 256), i2 = IX(u4 + 512), i3 = IX(u4 + 768);
        float2 acc = make_float2(0.0f, 0.0f);
        float2 wc  = make_float2(1.0f, 0.0f);
        #pragma unroll
        for (int f1 = 0; f1 < 8; f1++) {
            int bb = f1 * 1024;
            float2 S0 = buf[bb + i0], S1 = buf[bb + i1];
            float2 S2 = buf[bb + i2], S3 = buf[bb + i3];
            float2 A = caddf(S0, S2), Bv = caddf(S1, S3);
            float2 C = csubf(S0, S2), D  = csubf(S1, S3);
            float2 Z;
            if      (r4 == 0) Z = caddf(A, Bv);
            else if (r4 == 1) Z = make_float2(C.x - D.y, C.y + D.x);   // C + iD
            else if (r4 == 2) Z = csubf(A, Bv);
            else              Z = make_float2(C.x + D.y, C.y - D.x);   // C - iD
            acc = caddf(acc, cmulf(Z, wc));
            wc = cmulf(wc, wb);
        }
        sA[o] = acc.x * invN;
        sB[o] = acc.y * invN;
    }
    __syncthreads();

    // ---- parallel exclusive prefix scan: 7 chunks x 128 per row, 2 rows ---
    // S[0]=0, S[i+1]=sum(cc[0..i]) (deterministic fixed tree order).
    int wid  = threadIdx.x >> 5;
    int lane = threadIdx.x & 31;
    int row  = wid >> 3;          // 0 -> A, 1 -> B
    int ch   = wid & 7;           // chunk 0..7 (7 idle)
    const float* Ssrc = row ? sB : sA;
    float v[4];
    if (ch < 7) {
        float run = 0.0f;
        #pragma unroll
        for (int q = 0; q < 4; q++) {
            float x = Ssrc[ch * 128 + q * 32 + lane];
            #pragma unroll
            for (int off = 1; off < 32; off <<= 1) {
                float t = __shfl_up_sync(0xffffffffu, x, off);
                if (lane >= off) x += t;
            }
            v[q] = run + x;                       // inclusive within chunk
            run += __shfl_sync(0xffffffffu, x, 31);
        }
        if (lane == 0) chtot[row * 8 + ch] = run;
    }
    __syncthreads();
    if (ch < 7) {
        float offv = 0.0f;
        for (int c = 0; c < ch; c++) offv += chtot[row * 8 + c];
        float* Gdst = &g_cc[((size_t)bk * PC + 2 * pp + row) * CCS];
        #pragma unroll
        for (int q = 0; q < 4; q++)
            Gdst[ch * 128 + q * 32 + lane + 1] = offv + v[q];
        if (ch == 0 && lane == 0) Gdst[0] = 0.0f;
    }
}

// ---------------------------------------------------------------------------
// Kernel 3: SRP grid accumulation via prefix differences.
// Delay path mimics XLA:CPU partial-fast-math codegen — DO NOT CHANGE:
//   dist = sqrt( fma(dx, dx, dy*dy) ); x = (d_i-d_j)*fl(16000/343);
//   delay = roundeven(x) + N/2
// ---------------------------------------------------------------------------
__global__ __launch_bounds__(GD)
void grid_kernel(const float* __restrict__ mic,
                 const float* __restrict__ room,
                 float* __restrict__ out) {
    __shared__ float wred[4];
    int bid = blockIdx.x;
    int bk  = bid >> 7;          // /128
    int gi  = bid & 127;
    int b   = bk >> 2;           // /K
    int gj  = threadIdx.x;

    const float step = 1.0f / 127.0f;
    float tx = __fmul_rn((float)gi, step);
    float ty = __fmul_rn((float)gj, step);
    float gx = __fmul_rn(__ldg(&room[b * 3 + 0]), tx);
    float gy = __fmul_rn(__ldg(&room[b * 3 + 1]), ty);

    float d[4];
    #pragma unroll
    for (int m = 0; m < 4; m++) {
        float mx = __ldg(&mic[((size_t)bk * MC + m) * 3 + 0]);
        float my = __ldg(&mic[((size_t)bk * MC + m) * 3 + 1]);
        float dx = __fsub_rn(gx, mx);
        float dy = __fsub_rn(gy, my);
        float dy2 = __fmul_rn(dy, dy);
        d[m] = sqrtf(__fmaf_rn(dx, dx, dy2));   // LLVM contraction order
    }

    const float SCALE = __fdiv_rn(16000.0f, 343.0f);  // fl(16000/343)

    const int ii[PC] = {0, 0, 0, 1, 1, 2};
    const int jj[PC] = {1, 2, 3, 2, 3, 3};
    float acc = 0.0f;
    #pragma unroll
    for (int p = 0; p < PC; p++) {
        float x     = __fmul_rn(__fsub_rn(d[ii[p]], d[jj[p]]), SCALE);
        int   delay = (int)rintf(x) + HALF;                   // half-even
        const float* S = &g_cc[((size_t)bk * PC + p) * CCS];
        int base = delay - 5 - CCLO;
        base = min(max(base, 0), CCS - 11);                   // safety, never binds
        acc += __ldg(&S[base + 10]) - __ldg(&S[base]);
    }
    out[(size_t)bk * (GD * GD) + gi * GD + gj] = acc;

    // block max -> atomicMax (order-independent -> deterministic)
    float mx = acc;
    #pragma unroll
    for (int o = 16; o; o >>= 1)
        mx = fmaxf(mx, __shfl_xor_sync(0xffffffffu, mx, o));
    if ((threadIdx.x & 31) == 0) wred[threadIdx.x >> 5] = mx;
    __syncthreads();
    if (threadIdx.x == 0) {
        mx = fmaxf(fmaxf(wred[0], wred[1]), fmaxf(wred[2], wred[3]));
        atomicMax(&g_maxenc[bk], enc_f(mx));
    }
}

// ---------------------------------------------------------------------------
// Kernel 4: wide vectorized divide by per-(b,k) max (measured-best shape).
// ---------------------------------------------------------------------------
__global__ __launch_bounds__(256)
void divide_kernel(float* __restrict__ out) {
    int i  = blockIdx.x * 256 + threadIdx.x;   // float4 index, [0, 256K)
    int bk = i >> 12;                          // 4096 float4 per (b,k)
    float m = dec_f(g_maxenc[bk]);
    float4 v = reinterpret_cast<float4*>(out)[i];
    v.x = __fdiv_rn(v.x, m);
    v.y = __fdiv_rn(v.y, m);
    v.z = __fdiv_rn(v.z, m);
    v.w = __fdiv_rn(v.w, m);
    reinterpret_cast<float4*>(out)[i] = v;
}

// ---------------------------------------------------------------------------
extern "C" void kernel_launch(void* const* d_in, const int* in_sizes, int n_in,
                              void* d_out, int out_size) {
    const float* signal = (const float*)d_in[0];  // (B,K,M,N)
    const float* mic    = (const float*)d_in[1];  // (B,K,M,3)
    const float* room   = (const float*)d_in[2];  // (B,3)
    float* out = (float*)d_out;                   // (B,K,G*G)

    const int smem_fwd   = (NFFT + TWN) * (int)sizeof(float2);                       // 68 KB
    const int smem_cross = smem_fwd + 2 * CCN * (int)sizeof(float);                  // 75.2 KB
    cudaFuncSetAttribute(fwd_fft_kernel,    cudaFuncAttributeMaxDynamicSharedMemorySize, smem_fwd);
    cudaFuncSetAttribute(cross_ifft_kernel, cudaFuncAttributeMaxDynamicSharedMemorySize, smem_cross);

    fwd_fft_kernel<<<BKC * 2, TFT, smem_fwd>>>(signal);
    cross_ifft_kernel<<<BKC * 3, TFT, smem_cross>>>();
    grid_kernel<<<BKC * GD, GD>>>(mic, room, out);
    divide_kernel<<<(BKC * GD * GD / 4) / 256, 256>>>(out);
}